// round 1
// baseline (speedup 1.0000x reference)
#include <cuda_runtime.h>
#include <cstdint>
#include <math.h>

#define BATCH 4096
#define DM    768
#define NT    124
#define NRT   10240

// ---- group tables ----
__constant__ int c_shift[5] = {9, 8, 7, 6, 5};          // log2(r) per group
__constant__ int c_tbase[5] = {0, 4, 12, 28, 60};       // transform index prefix
__constant__ int c_n[5]     = {4, 8, 16, 32, 64};
__constant__ unsigned long long c_goff[5] = {3145730ull, 3162114ull, 3194882ull, 3260418ull, 3391490ull};

#define SP_OFF  3145728ull
#define ACT_OFF 3145729ull

// ---- scratch (static device memory: allowed; no allocations) ----
__device__ __align__(16) float g_Y[(size_t)BATCH * NRT];   // 167.8 MB
__device__ __align__(16) float g_W[(size_t)NRT * DM];      // 31.5 MB  (U transposed, concatenated)
__device__ __align__(16) float g_ENC[NT * DM];
__device__ float g_BIAS[NT];
__device__ __align__(16) float g_GATE[(size_t)BATCH * 128];
__device__ float g_SQV[NT];
__device__ float g_SQU[NT];
__device__ float g_SABS[NT];
__device__ float g_CNT[NT];

struct P5 { const float* p[5]; };

__device__ __forceinline__ void decode_t(int t, int& g, int& tl) {
    if (t < 4)       { g = 0; tl = t; }
    else if (t < 12) { g = 1; tl = t - 4; }
    else if (t < 28) { g = 2; tl = t - 12; }
    else if (t < 60) { g = 3; tl = t - 28; }
    else             { g = 4; tl = t - 60; }
}

// ---- packed f32x2 helpers (Blackwell FFMA2) ----
__device__ __forceinline__ unsigned long long pk2(float lo, float hi) {
    unsigned long long d;
    asm("mov.b64 %0, {%1, %2};" : "=l"(d) : "f"(lo), "f"(hi));
    return d;
}
__device__ __forceinline__ void upk2(unsigned long long d, float& lo, float& hi) {
    asm("mov.b64 {%0, %1}, %2;" : "=f"(lo), "=f"(hi) : "l"(d));
}
#define FMA2(accv, av, bv) asm("fma.rn.f32x2 %0, %1, %2, %0;" : "+l"(accv) : "l"(av), "l"(bv))

__device__ __forceinline__ float blk_reduce256(float v) {
    __shared__ float sh[256];
    int tid = threadIdx.x;
    sh[tid] = v;
    __syncthreads();
    for (int s = 128; s > 0; s >>= 1) {
        if (tid < s) sh[tid] += sh[tid + s];
        __syncthreads();
    }
    float r = sh[0];
    __syncthreads();
    return r;
}

// ============================================================
// prep: gather enc/bias into contiguous scratch
// ============================================================
__global__ void prep_enc(P5 E, P5 Bv) {
    int t = blockIdx.x;
    int g, tl; decode_t(t, g, tl);
    const float* src = E.p[g] + (size_t)tl * DM;
    for (int i = threadIdx.x; i < DM; i += blockDim.x)
        g_ENC[t * DM + i] = src[i];
    if (threadIdx.x == 0) g_BIAS[t] = Bv.p[g][tl];
}

// ============================================================
// prep: transpose U (n, 768, r) -> W rows (wbase + t*r + j, dd)
// ============================================================
__global__ void transpose_u(const float* __restrict__ U, int r, int wbase) {
    __shared__ float tile[32][33];
    int t  = blockIdx.z;
    int j0 = blockIdx.x * 32;
    int d0 = blockIdx.y * 32;
    const float* u = U + (size_t)t * DM * r;
#pragma unroll
    for (int i = 0; i < 4; i++) {
        int dl = threadIdx.y * 4 + i;
        tile[dl][threadIdx.x] = u[(size_t)(d0 + dl) * r + j0 + threadIdx.x];
    }
    __syncthreads();
#pragma unroll
    for (int i = 0; i < 4; i++) {
        int jl = threadIdx.y * 4 + i;
        g_W[(size_t)(wbase + t * r + j0 + jl) * DM + d0 + threadIdx.x] = tile[threadIdx.x][jl];
    }
}

// ============================================================
// Frobenius norm sums of squares per transform
// ============================================================
__global__ void norms_kernel(P5 V, P5 U) {
    int t = blockIdx.x;
    int g, tl; decode_t(t, g, tl);
    int r = 512 >> g;
    size_t n = (size_t)r * DM;
    const float* v = V.p[g] + (size_t)tl * n;
    const float* u = U.p[g] + (size_t)tl * n;
    float sv = 0.f, su = 0.f;
    for (size_t i = threadIdx.x; i < n; i += 256) {
        float a = v[i]; sv += a * a;
        float b = u[i]; su += b * b;
    }
    sv = blk_reduce256(sv);
    su = blk_reduce256(su);
    if (threadIdx.x == 0) { g_SQV[t] = sv; g_SQU[t] = su; }
}

// ============================================================
// gates: gate[b,t] = relu(x[b]·enc_t - bias_t), written to scratch + outputs
// block: 32 batch rows x 124 transforms; 256 threads = 32 rows x 8 chunks(16 cols)
// ============================================================
__global__ void gate_kernel(const float* __restrict__ X, float* __restrict__ out) {
    __shared__ float xs[32][33];
    __shared__ float es[32][129];
    int tid = threadIdx.x;
    int row = tid & 31, chunk = tid >> 5;
    int brow = blockIdx.x * 32;
    float acc[16];
#pragma unroll
    for (int c = 0; c < 16; c++) acc[c] = 0.f;

    for (int k0 = 0; k0 < DM; k0 += 32) {
        for (int i = tid; i < 32 * 32; i += 256) {
            int rr = i >> 5, kk = i & 31;
            xs[rr][kk] = X[(size_t)(brow + rr) * DM + k0 + kk];
        }
        for (int i = tid; i < NT * 32; i += 256) {
            int t = i >> 5, kk = i & 31;
            es[kk][t] = g_ENC[t * DM + k0 + kk];
        }
        __syncthreads();
#pragma unroll 8
        for (int kk = 0; kk < 32; kk++) {
            float xv = xs[row][kk];
#pragma unroll
            for (int c = 0; c < 16; c++) acc[c] += xv * es[kk][chunk * 16 + c];
        }
        __syncthreads();
    }

    int b = brow + row;
#pragma unroll
    for (int c = 0; c < 16; c++) {
        int t = chunk * 16 + c;
        if (t < NT) {
            float pre = acc[c] - g_BIAS[t];
            float gv  = pre > 0.f ? pre : 0.f;
            g_GATE[(size_t)b * 128 + t] = gv;
            int g, tl; decode_t(t, g, tl);
            out[c_goff[g] + (size_t)b * c_n[g] + tl] = gv;
        }
    }
}

// ============================================================
// gate statistics per transform
// ============================================================
__global__ void gate_stats() {
    int t = blockIdx.x;
    float sa = 0.f, cnt = 0.f;
    for (int b = threadIdx.x; b < BATCH; b += 256) {
        float gg = g_GATE[(size_t)b * 128 + t];
        sa  += fabsf(gg);
        cnt += (gg > 0.f) ? 1.f : 0.f;
    }
    sa  = blk_reduce256(sa);
    cnt = blk_reduce256(cnt);
    if (threadIdx.x == 0) { g_SABS[t] = sa; g_CNT[t] = cnt; }
}

// ============================================================
// scalars
// ============================================================
__global__ void finalize_kernel(float* __restrict__ out) {
    int t = threadIdx.x;  // 128 threads
    float sp = 0.f, act = 0.f;
    if (t < NT) {
        int g, tl; decode_t(t, g, tl);
        int r = 512 >> g;
        float frob = sqrtf(g_SQU[t] * g_SQV[t]) * rsqrtf((float)(DM * r));
        sp  = tanhf(g_SABS[t] / (float)BATCH) * frob;
        act = g_CNT[t];
    }
    __shared__ float s1[128], s2[128];
    s1[t] = sp; s2[t] = act;
    __syncthreads();
    for (int s = 64; s > 0; s >>= 1) {
        if (t < s) { s1[t] += s1[t + s]; s2[t] += s2[t + s]; }
        __syncthreads();
    }
    if (t == 0) {
        out[SP_OFF]  = s1[0];
        out[ACT_OFF] = s2[0] / (float)BATCH;
    }
}

// ============================================================
// GEMM1: Y[b, col] = (X @ Vcat^T)[b,col] * gate[b, t(col)]
// NT-layout (both K-major). 128x128x16 tiles, 256 thr, 8x8 micro, f32x2 FMA
// ============================================================
__global__ void __launch_bounds__(256, 2)
gemm1_kernel(const float* __restrict__ X, P5 V) {
    __shared__ __align__(16) float As[16][136];
    __shared__ __align__(16) float Bs[16][136];
    const int tid  = threadIdx.x;
    const int colg = blockIdx.x * 128;       // global column
    const int g    = colg >> 11;
    const int col_local = colg & 2047;
    const float* __restrict__ Bmat = V.p[g] + (size_t)col_local * DM;
    const int bm = blockIdx.y * 128;

    const int lrow = tid >> 2;               // 0..63
    const int lk4  = (tid & 3) << 2;         // 0,4,8,12
    const float* Ap = X    + (size_t)(bm + lrow) * DM + lk4;
    const float* Bp = Bmat + (size_t)lrow * DM + lk4;

    const int tx = tid & 15, ty = tid >> 4;

    unsigned long long acc[8][4];
#pragma unroll
    for (int i = 0; i < 8; i++)
#pragma unroll
        for (int j = 0; j < 4; j++) acc[i][j] = 0ull;

    for (int k0 = 0; k0 < DM; k0 += 16) {
        float4 a0 = *(const float4*)(Ap + k0);
        float4 a1 = *(const float4*)(Ap + (size_t)64 * DM + k0);
        float4 b0 = *(const float4*)(Bp + k0);
        float4 b1 = *(const float4*)(Bp + (size_t)64 * DM + k0);
        __syncthreads();
        As[lk4 + 0][lrow] = a0.x; As[lk4 + 1][lrow] = a0.y; As[lk4 + 2][lrow] = a0.z; As[lk4 + 3][lrow] = a0.w;
        As[lk4 + 0][lrow + 64] = a1.x; As[lk4 + 1][lrow + 64] = a1.y; As[lk4 + 2][lrow + 64] = a1.z; As[lk4 + 3][lrow + 64] = a1.w;
        Bs[lk4 + 0][lrow] = b0.x; Bs[lk4 + 1][lrow] = b0.y; Bs[lk4 + 2][lrow] = b0.z; Bs[lk4 + 3][lrow] = b0.w;
        Bs[lk4 + 0][lrow + 64] = b1.x; Bs[lk4 + 1][lrow + 64] = b1.y; Bs[lk4 + 2][lrow + 64] = b1.z; Bs[lk4 + 3][lrow + 64] = b1.w;
        __syncthreads();
#pragma unroll
        for (int kk = 0; kk < 16; kk++) {
            float4 av0 = *(const float4*)&As[kk][ty * 8];
            float4 av1 = *(const float4*)&As[kk][ty * 8 + 4];
            float4 bv0 = *(const float4*)&Bs[kk][tx * 8];
            float4 bv1 = *(const float4*)&Bs[kk][tx * 8 + 4];
            unsigned long long b2[4] = { pk2(bv0.x, bv0.y), pk2(bv0.z, bv0.w),
                                         pk2(bv1.x, bv1.y), pk2(bv1.z, bv1.w) };
            float a_[8] = {av0.x, av0.y, av0.z, av0.w, av1.x, av1.y, av1.z, av1.w};
#pragma unroll
            for (int i = 0; i < 8; i++) {
                unsigned long long a2 = pk2(a_[i], a_[i]);
#pragma unroll
                for (int j = 0; j < 4; j++) FMA2(acc[i][j], a2, b2[j]);
            }
        }
    }

    const int shift = c_shift[g];
    const int tbase = c_tbase[g];
#pragma unroll
    for (int i = 0; i < 8; i++) {
        int row = bm + ty * 8 + i;
        const float* grow = g_GATE + (size_t)row * 128;
        float c8[8];
#pragma unroll
        for (int j = 0; j < 4; j++) upk2(acc[i][j], c8[2 * j], c8[2 * j + 1]);
#pragma unroll
        for (int j = 0; j < 8; j++) {
            int cl = col_local + tx * 8 + j;
            int t  = tbase + (cl >> shift);
            c8[j] *= grow[t];
        }
        float* yrow = g_Y + (size_t)row * NRT + colg + tx * 8;
        *(float4*)(yrow)     = make_float4(c8[0], c8[1], c8[2], c8[3]);
        *(float4*)(yrow + 4) = make_float4(c8[4], c8[5], c8[6], c8[7]);
    }
}

// ============================================================
// GEMM2: OUT = Yg @ Wcat   (NN, K = 10240)
// ============================================================
__global__ void __launch_bounds__(256, 2)
gemm2_kernel(float* __restrict__ OUT) {
    __shared__ __align__(16) float As[16][136];
    __shared__ __align__(16) float Bs[16][136];
    const int tid = threadIdx.x;
    const int bn  = blockIdx.x * 128;
    const int bm  = blockIdx.y * 128;

    const int lrow = tid >> 2;
    const int lk4  = (tid & 3) << 2;
    const float* Ap = g_Y + (size_t)(bm + lrow) * NRT + lk4;

    const int bkr = tid >> 5;          // 0..7
    const int bc4 = (tid & 31) << 2;   // 0..124

    const int tx = tid & 15, ty = tid >> 4;

    unsigned long long acc[8][4];
#pragma unroll
    for (int i = 0; i < 8; i++)
#pragma unroll
        for (int j = 0; j < 4; j++) acc[i][j] = 0ull;

    for (int k0 = 0; k0 < NRT; k0 += 16) {
        float4 a0 = *(const float4*)(Ap + k0);
        float4 a1 = *(const float4*)(Ap + (size_t)64 * NRT + k0);
        float4 w0 = *(const float4*)(g_W + (size_t)(k0 + bkr) * DM + bn + bc4);
        float4 w1 = *(const float4*)(g_W + (size_t)(k0 + bkr + 8) * DM + bn + bc4);
        __syncthreads();
        As[lk4 + 0][lrow] = a0.x; As[lk4 + 1][lrow] = a0.y; As[lk4 + 2][lrow] = a0.z; As[lk4 + 3][lrow] = a0.w;
        As[lk4 + 0][lrow + 64] = a1.x; As[lk4 + 1][lrow + 64] = a1.y; As[lk4 + 2][lrow + 64] = a1.z; As[lk4 + 3][lrow + 64] = a1.w;
        *(float4*)&Bs[bkr][bc4]     = w0;
        *(float4*)&Bs[bkr + 8][bc4] = w1;
        __syncthreads();
#pragma unroll
        for (int kk = 0; kk < 16; kk++) {
            float4 av0 = *(const float4*)&As[kk][ty * 8];
            float4 av1 = *(const float4*)&As[kk][ty * 8 + 4];
            float4 bv0 = *(const float4*)&Bs[kk][tx * 8];
            float4 bv1 = *(const float4*)&Bs[kk][tx * 8 + 4];
            unsigned long long b2[4] = { pk2(bv0.x, bv0.y), pk2(bv0.z, bv0.w),
                                         pk2(bv1.x, bv1.y), pk2(bv1.z, bv1.w) };
            float a_[8] = {av0.x, av0.y, av0.z, av0.w, av1.x, av1.y, av1.z, av1.w};
#pragma unroll
            for (int i = 0; i < 8; i++) {
                unsigned long long a2 = pk2(a_[i], a_[i]);
#pragma unroll
                for (int j = 0; j < 4; j++) FMA2(acc[i][j], a2, b2[j]);
            }
        }
    }

#pragma unroll
    for (int i = 0; i < 8; i++) {
        int row = bm + ty * 8 + i;
        float c8[8];
#pragma unroll
        for (int j = 0; j < 4; j++) upk2(acc[i][j], c8[2 * j], c8[2 * j + 1]);
        float* o = OUT + (size_t)row * DM + bn + tx * 8;
        *(float4*)(o)     = make_float4(c8[0], c8[1], c8[2], c8[3]);
        *(float4*)(o + 4) = make_float4(c8[4], c8[5], c8[6], c8[7]);
    }
}

// ============================================================
// launch
// ============================================================
extern "C" void kernel_launch(void* const* d_in, const int* in_sizes, int n_in,
                              void* d_out, int out_size) {
    (void)in_sizes; (void)n_in; (void)out_size;
    const float* x = (const float*)d_in[0];
    P5 V, U, E, Bv;
    const int nn[5] = {4, 8, 16, 32, 64};
    const int rr[5] = {512, 256, 128, 64, 32};
    for (int g = 0; g < 5; g++) {
        V.p[g]  = (const float*)d_in[1 + 4 * g];
        U.p[g]  = (const float*)d_in[2 + 4 * g];
        E.p[g]  = (const float*)d_in[3 + 4 * g];
        Bv.p[g] = (const float*)d_in[4 + 4 * g];
    }
    float* out = (float*)d_out;

    prep_enc<<<NT, 256>>>(E, Bv);
    for (int g = 0; g < 5; g++)
        transpose_u<<<dim3(rr[g] / 32, DM / 32, nn[g]), dim3(32, 8)>>>(U.p[g], rr[g], g * 2048);
    norms_kernel<<<NT, 256>>>(V, U);
    gate_kernel<<<BATCH / 32, 256>>>(x, out);
    gate_stats<<<NT, 256>>>();
    finalize_kernel<<<1, 128>>>(out);
    gemm1_kernel<<<dim3(NRT / 128, BATCH / 128), 256>>>(x, V);
    gemm2_kernel<<<dim3(DM / 128, BATCH / 128), 256>>>(out);
}

// round 2
// speedup vs baseline: 1.0044x; 1.0044x over previous
#include <cuda_runtime.h>
#include <cstdint>
#include <math.h>

#define BATCH 4096
#define DM    768
#define NT    124
#define NRT   10240

// ---- group tables ----
__constant__ int c_shift[5] = {9, 8, 7, 6, 5};          // log2(r) per group
__constant__ int c_tbase[5] = {0, 4, 12, 28, 60};       // transform index prefix
__constant__ int c_n[5]     = {4, 8, 16, 32, 64};
__constant__ unsigned long long c_goff[5] = {3145730ull, 3162114ull, 3194882ull, 3260418ull, 3391490ull};

#define SP_OFF  3145728ull
#define ACT_OFF 3145729ull

// ---- scratch (static device memory: allowed; no allocations) ----
__device__ __align__(16) float g_Y[(size_t)BATCH * NRT];   // 167.8 MB
__device__ __align__(16) float g_W[(size_t)NRT * DM];      // 31.5 MB  (U transposed, concatenated)
__device__ __align__(16) float g_ENC[NT * DM];
__device__ float g_BIAS[NT];
__device__ __align__(16) float g_GATE[(size_t)BATCH * 128];
__device__ float g_SQV[NT];
__device__ float g_SQU[NT];
__device__ float g_SABS[NT];
__device__ float g_CNT[NT];

struct P5 { const float* p[5]; };

__device__ __forceinline__ void decode_t(int t, int& g, int& tl) {
    if (t < 4)       { g = 0; tl = t; }
    else if (t < 12) { g = 1; tl = t - 4; }
    else if (t < 28) { g = 2; tl = t - 12; }
    else if (t < 60) { g = 3; tl = t - 28; }
    else             { g = 4; tl = t - 60; }
}

// ---- packed f32x2 helpers (Blackwell FFMA2) ----
__device__ __forceinline__ unsigned long long pk2(float lo, float hi) {
    unsigned long long d;
    asm("mov.b64 %0, {%1, %2};" : "=l"(d) : "f"(lo), "f"(hi));
    return d;
}
__device__ __forceinline__ void upk2(unsigned long long d, float& lo, float& hi) {
    asm("mov.b64 {%0, %1}, %2;" : "=f"(lo), "=f"(hi) : "l"(d));
}
#define FMA2(accv, av, bv) asm("fma.rn.f32x2 %0, %1, %2, %0;" : "+l"(accv) : "l"(av), "l"(bv))

__device__ __forceinline__ float blk_reduce256(float v) {
    __shared__ float sh[256];
    int tid = threadIdx.x;
    sh[tid] = v;
    __syncthreads();
    for (int s = 128; s > 0; s >>= 1) {
        if (tid < s) sh[tid] += sh[tid + s];
        __syncthreads();
    }
    float r = sh[0];
    __syncthreads();
    return r;
}

// ============================================================
// prep: gather enc/bias into contiguous scratch
// ============================================================
__global__ void prep_enc(P5 E, P5 Bv) {
    int t = blockIdx.x;
    int g, tl; decode_t(t, g, tl);
    const float* src = E.p[g] + (size_t)tl * DM;
    for (int i = threadIdx.x; i < DM; i += blockDim.x)
        g_ENC[t * DM + i] = src[i];
    if (threadIdx.x == 0) g_BIAS[t] = Bv.p[g][tl];
}

// ============================================================
// prep: transpose U (n, 768, r) -> W rows (wbase + t*r + j, dd)
// ============================================================
__global__ void transpose_u(const float* __restrict__ U, int r, int wbase) {
    __shared__ float tile[32][33];
    int t  = blockIdx.z;
    int j0 = blockIdx.x * 32;
    int d0 = blockIdx.y * 32;
    const float* u = U + (size_t)t * DM * r;
#pragma unroll
    for (int i = 0; i < 4; i++) {
        int dl = threadIdx.y * 4 + i;
        tile[dl][threadIdx.x] = u[(size_t)(d0 + dl) * r + j0 + threadIdx.x];
    }
    __syncthreads();
#pragma unroll
    for (int i = 0; i < 4; i++) {
        int jl = threadIdx.y * 4 + i;
        g_W[(size_t)(wbase + t * r + j0 + jl) * DM + d0 + threadIdx.x] = tile[threadIdx.x][jl];
    }
}

// ============================================================
// Frobenius norm sums of squares per transform
// ============================================================
__global__ void norms_kernel(P5 V, P5 U) {
    int t = blockIdx.x;
    int g, tl; decode_t(t, g, tl);
    int r = 512 >> g;
    size_t n = (size_t)r * DM;
    const float* v = V.p[g] + (size_t)tl * n;
    const float* u = U.p[g] + (size_t)tl * n;
    float sv = 0.f, su = 0.f;
    for (size_t i = threadIdx.x; i < n; i += 256) {
        float a = v[i]; sv += a * a;
        float b = u[i]; su += b * b;
    }
    sv = blk_reduce256(sv);
    su = blk_reduce256(su);
    if (threadIdx.x == 0) { g_SQV[t] = sv; g_SQU[t] = su; }
}

// ============================================================
// gates: gate[b,t] = relu(x[b]·enc_t - bias_t), written to scratch + outputs
// block: 32 batch rows x 124 transforms; 256 threads = 32 rows x 8 chunks(16 cols)
// ============================================================
__global__ void gate_kernel(const float* __restrict__ X, float* __restrict__ out) {
    __shared__ float xs[32][33];
    __shared__ float es[32][129];
    int tid = threadIdx.x;
    int row = tid & 31, chunk = tid >> 5;
    int brow = blockIdx.x * 32;
    float acc[16];
#pragma unroll
    for (int c = 0; c < 16; c++) acc[c] = 0.f;

    for (int k0 = 0; k0 < DM; k0 += 32) {
        for (int i = tid; i < 32 * 32; i += 256) {
            int rr = i >> 5, kk = i & 31;
            xs[rr][kk] = X[(size_t)(brow + rr) * DM + k0 + kk];
        }
        for (int i = tid; i < NT * 32; i += 256) {
            int t = i >> 5, kk = i & 31;
            es[kk][t] = g_ENC[t * DM + k0 + kk];
        }
        __syncthreads();
#pragma unroll 8
        for (int kk = 0; kk < 32; kk++) {
            float xv = xs[row][kk];
#pragma unroll
            for (int c = 0; c < 16; c++) acc[c] += xv * es[kk][chunk * 16 + c];
        }
        __syncthreads();
    }

    int b = brow + row;
#pragma unroll
    for (int c = 0; c < 16; c++) {
        int t = chunk * 16 + c;
        if (t < NT) {
            float pre = acc[c] - g_BIAS[t];
            float gv  = pre > 0.f ? pre : 0.f;
            g_GATE[(size_t)b * 128 + t] = gv;
            int g, tl; decode_t(t, g, tl);
            out[c_goff[g] + (size_t)b * c_n[g] + tl] = gv;
        }
    }
}

// ============================================================
// gate statistics per transform
// ============================================================
__global__ void gate_stats() {
    int t = blockIdx.x;
    float sa = 0.f, cnt = 0.f;
    for (int b = threadIdx.x; b < BATCH; b += 256) {
        float gg = g_GATE[(size_t)b * 128 + t];
        sa  += fabsf(gg);
        cnt += (gg > 0.f) ? 1.f : 0.f;
    }
    sa  = blk_reduce256(sa);
    cnt = blk_reduce256(cnt);
    if (threadIdx.x == 0) { g_SABS[t] = sa; g_CNT[t] = cnt; }
}

// ============================================================
// scalars
// ============================================================
__global__ void finalize_kernel(float* __restrict__ out) {
    int t = threadIdx.x;  // 128 threads
    float sp = 0.f, act = 0.f;
    if (t < NT) {
        int g, tl; decode_t(t, g, tl);
        int r = 512 >> g;
        float frob = sqrtf(g_SQU[t] * g_SQV[t]) * rsqrtf((float)(DM * r));
        sp  = tanhf(g_SABS[t] / (float)BATCH) * frob;
        act = g_CNT[t];
    }
    __shared__ float s1[128], s2[128];
    s1[t] = sp; s2[t] = act;
    __syncthreads();
    for (int s = 64; s > 0; s >>= 1) {
        if (t < s) { s1[t] += s1[t + s]; s2[t] += s2[t + s]; }
        __syncthreads();
    }
    if (t == 0) {
        out[SP_OFF]  = s1[0];
        out[ACT_OFF] = s2[0] / (float)BATCH;
    }
}

// ============================================================
// GEMM1: Y[b, col] = (X @ Vcat^T)[b,col] * gate[b, t(col)]
// NT-layout (both K-major). 128x128x16 tiles, 256 thr, 8x8 micro, f32x2 FMA
// ============================================================
__global__ void __launch_bounds__(256, 2)
gemm1_kernel(const float* __restrict__ X, P5 V) {
    __shared__ __align__(16) float As[16][136];
    __shared__ __align__(16) float Bs[16][136];
    const int tid  = threadIdx.x;
    const int colg = blockIdx.x * 128;       // global column
    const int g    = colg >> 11;
    const int col_local = colg & 2047;
    const float* __restrict__ Bmat = V.p[g] + (size_t)col_local * DM;
    const int bm = blockIdx.y * 128;

    const int lrow = tid >> 2;               // 0..63
    const int lk4  = (tid & 3) << 2;         // 0,4,8,12
    const float* Ap = X    + (size_t)(bm + lrow) * DM + lk4;
    const float* Bp = Bmat + (size_t)lrow * DM + lk4;

    const int tx = tid & 15, ty = tid >> 4;

    unsigned long long acc[8][4];
#pragma unroll
    for (int i = 0; i < 8; i++)
#pragma unroll
        for (int j = 0; j < 4; j++) acc[i][j] = 0ull;

    for (int k0 = 0; k0 < DM; k0 += 16) {
        float4 a0 = *(const float4*)(Ap + k0);
        float4 a1 = *(const float4*)(Ap + (size_t)64 * DM + k0);
        float4 b0 = *(const float4*)(Bp + k0);
        float4 b1 = *(const float4*)(Bp + (size_t)64 * DM + k0);
        __syncthreads();
        As[lk4 + 0][lrow] = a0.x; As[lk4 + 1][lrow] = a0.y; As[lk4 + 2][lrow] = a0.z; As[lk4 + 3][lrow] = a0.w;
        As[lk4 + 0][lrow + 64] = a1.x; As[lk4 + 1][lrow + 64] = a1.y; As[lk4 + 2][lrow + 64] = a1.z; As[lk4 + 3][lrow + 64] = a1.w;
        Bs[lk4 + 0][lrow] = b0.x; Bs[lk4 + 1][lrow] = b0.y; Bs[lk4 + 2][lrow] = b0.z; Bs[lk4 + 3][lrow] = b0.w;
        Bs[lk4 + 0][lrow + 64] = b1.x; Bs[lk4 + 1][lrow + 64] = b1.y; Bs[lk4 + 2][lrow + 64] = b1.z; Bs[lk4 + 3][lrow + 64] = b1.w;
        __syncthreads();
#pragma unroll
        for (int kk = 0; kk < 16; kk++) {
            float4 av0 = *(const float4*)&As[kk][ty * 8];
            float4 av1 = *(const float4*)&As[kk][ty * 8 + 4];
            float4 bv0 = *(const float4*)&Bs[kk][tx * 8];
            float4 bv1 = *(const float4*)&Bs[kk][tx * 8 + 4];
            unsigned long long b2[4] = { pk2(bv0.x, bv0.y), pk2(bv0.z, bv0.w),
                                         pk2(bv1.x, bv1.y), pk2(bv1.z, bv1.w) };
            float a_[8] = {av0.x, av0.y, av0.z, av0.w, av1.x, av1.y, av1.z, av1.w};
#pragma unroll
            for (int i = 0; i < 8; i++) {
                unsigned long long a2 = pk2(a_[i], a_[i]);
#pragma unroll
                for (int j = 0; j < 4; j++) FMA2(acc[i][j], a2, b2[j]);
            }
        }
    }

    const int shift = c_shift[g];
    const int tbase = c_tbase[g];
#pragma unroll
    for (int i = 0; i < 8; i++) {
        int row = bm + ty * 8 + i;
        const float* grow = g_GATE + (size_t)row * 128;
        float c8[8];
#pragma unroll
        for (int j = 0; j < 4; j++) upk2(acc[i][j], c8[2 * j], c8[2 * j + 1]);
#pragma unroll
        for (int j = 0; j < 8; j++) {
            int cl = col_local + tx * 8 + j;
            int t  = tbase + (cl >> shift);
            c8[j] *= grow[t];
        }
        float* yrow = g_Y + (size_t)row * NRT + colg + tx * 8;
        *(float4*)(yrow)     = make_float4(c8[0], c8[1], c8[2], c8[3]);
        *(float4*)(yrow + 4) = make_float4(c8[4], c8[5], c8[6], c8[7]);
    }
}

// ============================================================
// GEMM2: OUT = Yg @ Wcat   (NN, K = 10240)
// ============================================================
__global__ void __launch_bounds__(256, 2)
gemm2_kernel(float* __restrict__ OUT) {
    __shared__ __align__(16) float As[16][136];
    __shared__ __align__(16) float Bs[16][136];
    const int tid = threadIdx.x;
    const int bn  = blockIdx.x * 128;
    const int bm  = blockIdx.y * 128;

    const int lrow = tid >> 2;
    const int lk4  = (tid & 3) << 2;
    const float* Ap = g_Y + (size_t)(bm + lrow) * NRT + lk4;

    const int bkr = tid >> 5;          // 0..7
    const int bc4 = (tid & 31) << 2;   // 0..124

    const int tx = tid & 15, ty = tid >> 4;

    unsigned long long acc[8][4];
#pragma unroll
    for (int i = 0; i < 8; i++)
#pragma unroll
        for (int j = 0; j < 4; j++) acc[i][j] = 0ull;

    for (int k0 = 0; k0 < NRT; k0 += 16) {
        float4 a0 = *(const float4*)(Ap + k0);
        float4 a1 = *(const float4*)(Ap + (size_t)64 * NRT + k0);
        float4 w0 = *(const float4*)(g_W + (size_t)(k0 + bkr) * DM + bn + bc4);
        float4 w1 = *(const float4*)(g_W + (size_t)(k0 + bkr + 8) * DM + bn + bc4);
        __syncthreads();
        As[lk4 + 0][lrow] = a0.x; As[lk4 + 1][lrow] = a0.y; As[lk4 + 2][lrow] = a0.z; As[lk4 + 3][lrow] = a0.w;
        As[lk4 + 0][lrow + 64] = a1.x; As[lk4 + 1][lrow + 64] = a1.y; As[lk4 + 2][lrow + 64] = a1.z; As[lk4 + 3][lrow + 64] = a1.w;
        *(float4*)&Bs[bkr][bc4]     = w0;
        *(float4*)&Bs[bkr + 8][bc4] = w1;
        __syncthreads();
#pragma unroll
        for (int kk = 0; kk < 16; kk++) {
            float4 av0 = *(const float4*)&As[kk][ty * 8];
            float4 av1 = *(const float4*)&As[kk][ty * 8 + 4];
            float4 bv0 = *(const float4*)&Bs[kk][tx * 8];
            float4 bv1 = *(const float4*)&Bs[kk][tx * 8 + 4];
            unsigned long long b2[4] = { pk2(bv0.x, bv0.y), pk2(bv0.z, bv0.w),
                                         pk2(bv1.x, bv1.y), pk2(bv1.z, bv1.w) };
            float a_[8] = {av0.x, av0.y, av0.z, av0.w, av1.x, av1.y, av1.z, av1.w};
#pragma unroll
            for (int i = 0; i < 8; i++) {
                unsigned long long a2 = pk2(a_[i], a_[i]);
#pragma unroll
                for (int j = 0; j < 4; j++) FMA2(acc[i][j], a2, b2[j]);
            }
        }
    }

#pragma unroll
    for (int i = 0; i < 8; i++) {
        int row = bm + ty * 8 + i;
        float c8[8];
#pragma unroll
        for (int j = 0; j < 4; j++) upk2(acc[i][j], c8[2 * j], c8[2 * j + 1]);
        float* o = OUT + (size_t)row * DM + bn + tx * 8;
        *(float4*)(o)     = make_float4(c8[0], c8[1], c8[2], c8[3]);
        *(float4*)(o + 4) = make_float4(c8[4], c8[5], c8[6], c8[7]);
    }
}

// ============================================================
// launch
// ============================================================
extern "C" void kernel_launch(void* const* d_in, const int* in_sizes, int n_in,
                              void* d_out, int out_size) {
    (void)in_sizes; (void)n_in; (void)out_size;
    const float* x = (const float*)d_in[0];
    P5 V, U, E, Bv;
    const int nn[5] = {4, 8, 16, 32, 64};
    const int rr[5] = {512, 256, 128, 64, 32};
    for (int g = 0; g < 5; g++) {
        V.p[g]  = (const float*)d_in[1 + 4 * g];
        U.p[g]  = (const float*)d_in[2 + 4 * g];
        E.p[g]  = (const float*)d_in[3 + 4 * g];
        Bv.p[g] = (const float*)d_in[4 + 4 * g];
    }
    float* out = (float*)d_out;

    prep_enc<<<NT, 256>>>(E, Bv);
    for (int g = 0; g < 5; g++)
        transpose_u<<<dim3(rr[g] / 32, DM / 32, nn[g]), dim3(32, 8)>>>(U.p[g], rr[g], g * 2048);
    norms_kernel<<<NT, 256>>>(V, U);
    gate_kernel<<<BATCH / 32, 256>>>(x, out);
    gate_stats<<<NT, 256>>>();
    finalize_kernel<<<1, 128>>>(out);
    gemm1_kernel<<<dim3(NRT / 128, BATCH / 128), 256>>>(x, V);
    gemm2_kernel<<<dim3(DM / 128, BATCH / 128), 256>>>(out);
}

// round 4
// speedup vs baseline: 3.1616x; 3.1477x over previous
#include <cuda_runtime.h>
#include <cstdint>
#include <math.h>

#define BATCH 4096
#define DM    768
#define NT    124
#define NRT   10240

__constant__ int c_shift[5] = {9, 8, 7, 6, 5};
__constant__ int c_tbase[5] = {0, 4, 12, 28, 60};
__constant__ int c_n[5]     = {4, 8, 16, 32, 64};
__constant__ unsigned long long c_goff[5] = {3145730ull, 3162114ull, 3194882ull, 3260418ull, 3391490ull};

#define SP_OFF  3145728ull
#define ACT_OFF 3145729ull

// ---- static device scratch ----
__device__ __align__(256) float g_Xr[(size_t)BATCH * DM];
__device__ __align__(256) float g_Vr[(size_t)NRT * DM];   // [10240][768] n-major, K rows
__device__ __align__(256) float g_W2[(size_t)DM * NRT];   // [768][10240] d-major, K cols
__device__ __align__(256) float g_Y[(size_t)BATCH * NRT];
__device__ __align__(256) float g_P[2ull * BATCH * DM];
__device__ __align__(16) float g_ENC[NT * DM];
__device__ float g_BIAS[NT];
__device__ __align__(16) float g_GATE[(size_t)BATCH * 128];
__device__ float g_SQV[NT];
__device__ float g_SQU[NT];
__device__ float g_SABS[NT];
__device__ float g_CNT[NT];

struct P5 { const float* p[5]; };

__device__ __forceinline__ void decode_t(int t, int& g, int& tl) {
    if (t < 4)       { g = 0; tl = t; }
    else if (t < 12) { g = 1; tl = t - 4; }
    else if (t < 28) { g = 2; tl = t - 12; }
    else if (t < 60) { g = 3; tl = t - 28; }
    else             { g = 4; tl = t - 60; }
}

__device__ __forceinline__ float blk_reduce256(float v) {
    __shared__ float sh[256];
    int tid = threadIdx.x;
    sh[tid] = v;
    __syncthreads();
    for (int s = 128; s > 0; s >>= 1) {
        if (tid < s) sh[tid] += sh[tid + s];
        __syncthreads();
    }
    float r = sh[0];
    __syncthreads();
    return r;
}

// ---- PTX helpers (all baseline sm_80+ PTX, no 'a'-features) ----
__device__ __forceinline__ uint32_t smem_u32(const void* p) {
    uint32_t a;
    asm("{ .reg .u64 t; cvta.to.shared.u64 t, %1; cvt.u32.u64 %0, t; }" : "=r"(a) : "l"(p));
    return a;
}
__device__ __forceinline__ float rna_tf32(float x) {
    uint32_t r;
    asm("cvt.rna.tf32.f32 %0, %1;" : "=r"(r) : "f"(x));
    return __uint_as_float(r);
}
__device__ __forceinline__ float4 rna4(float4 v) {
    v.x = rna_tf32(v.x); v.y = rna_tf32(v.y); v.z = rna_tf32(v.z); v.w = rna_tf32(v.w);
    return v;
}
__device__ __forceinline__ void cp16(uint32_t dst, const void* src) {
    asm volatile("cp.async.cg.shared.global [%0], [%1], 16;" :: "r"(dst), "l"(src) : "memory");
}
__device__ __forceinline__ void mma_tf32(float* d, const uint32_t* a, const uint32_t* b) {
    asm volatile("mma.sync.aligned.m16n8k8.row.col.f32.tf32.tf32.f32 "
        "{%0,%1,%2,%3}, {%4,%5,%6,%7}, {%8,%9}, {%0,%1,%2,%3};"
        : "+f"(d[0]), "+f"(d[1]), "+f"(d[2]), "+f"(d[3])
        : "r"(a[0]), "r"(a[1]), "r"(a[2]), "r"(a[3]), "r"(b[0]), "r"(b[1]));
}

// ============== prep kernels ==============
__global__ void prep_enc(P5 E, P5 Bv) {
    int t = blockIdx.x;
    int g, tl; decode_t(t, g, tl);
    const float* src = E.p[g] + (size_t)tl * DM;
    for (int i = threadIdx.x; i < DM; i += blockDim.x)
        g_ENC[t * DM + i] = src[i];
    if (threadIdx.x == 0) g_BIAS[t] = Bv.p[g][tl];
}

__global__ void rnd_x(const float* __restrict__ X) {
    int i4 = blockIdx.x * 256 + threadIdx.x;           // < 786432
    ((float4*)g_Xr)[i4] = rna4(((const float4*)X)[i4]);
}

__global__ void rnd_v(P5 V) {
    int i4 = blockIdx.x * 256 + threadIdx.x;           // < 1966080
    int n = i4 / 192, kq = i4 % 192;
    int g = n >> 11, lr = n & 2047;
    ((float4*)g_Vr)[(size_t)n * 192 + kq] = rna4(((const float4*)V.p[g])[(size_t)lr * 192 + kq]);
}

__global__ void build_w2(const float* __restrict__ U, int r, int g) {
    int i4 = blockIdx.x * 256 + threadIdx.x;           // < 393216 (n*768*r/4, n*r=2048)
    int rq = r >> 2;
    int t = i4 / (DM * rq);
    int rem = i4 % (DM * rq);
    int d = rem / rq, jq = rem % rq;
    float4 v = rna4(((const float4*)U)[(size_t)(t * DM + d) * rq + jq]);
    ((float4*)g_W2)[(size_t)d * 2560 + (g << 9) + t * rq + jq] = v;
}

// ============== exact f32 side computations ==============
__global__ void norms_kernel(P5 V, P5 U) {
    int t = blockIdx.x;
    int g, tl; decode_t(t, g, tl);
    int r = 512 >> g;
    size_t n = (size_t)r * DM;
    const float* v = V.p[g] + (size_t)tl * n;
    const float* u = U.p[g] + (size_t)tl * n;
    float sv = 0.f, su = 0.f;
    for (size_t i = threadIdx.x; i < n; i += 256) {
        float a = v[i]; sv += a * a;
        float b = u[i]; su += b * b;
    }
    sv = blk_reduce256(sv);
    su = blk_reduce256(su);
    if (threadIdx.x == 0) { g_SQV[t] = sv; g_SQU[t] = su; }
}

__global__ void gate_kernel(const float* __restrict__ X, float* __restrict__ out) {
    __shared__ float xs[32][33];
    __shared__ float es[32][129];
    int tid = threadIdx.x;
    int row = tid & 31, chunk = tid >> 5;
    int brow = blockIdx.x * 32;
    float acc[16];
#pragma unroll
    for (int c = 0; c < 16; c++) acc[c] = 0.f;
    for (int k0 = 0; k0 < DM; k0 += 32) {
        for (int i = tid; i < 32 * 32; i += 256) {
            int rr = i >> 5, kk = i & 31;
            xs[rr][kk] = X[(size_t)(brow + rr) * DM + k0 + kk];
        }
        for (int i = tid; i < NT * 32; i += 256) {
            int t = i >> 5, kk = i & 31;
            es[kk][t] = g_ENC[t * DM + k0 + kk];
        }
        __syncthreads();
#pragma unroll 8
        for (int kk = 0; kk < 32; kk++) {
            float xv = xs[row][kk];
#pragma unroll
            for (int c = 0; c < 16; c++) acc[c] += xv * es[kk][chunk * 16 + c];
        }
        __syncthreads();
    }
    int b = brow + row;
#pragma unroll
    for (int c = 0; c < 16; c++) {
        int t = chunk * 16 + c;
        if (t < NT) {
            float pre = acc[c] - g_BIAS[t];
            float gv  = pre > 0.f ? pre : 0.f;
            g_GATE[(size_t)b * 128 + t] = gv;
            int g, tl; decode_t(t, g, tl);
            out[c_goff[g] + (size_t)b * c_n[g] + tl] = gv;
        }
    }
}

__global__ void gate_stats() {
    int t = blockIdx.x;
    float sa = 0.f, cnt = 0.f;
    for (int b = threadIdx.x; b < BATCH; b += 256) {
        float gg = g_GATE[(size_t)b * 128 + t];
        sa  += fabsf(gg);
        cnt += (gg > 0.f) ? 1.f : 0.f;
    }
    sa  = blk_reduce256(sa);
    cnt = blk_reduce256(cnt);
    if (threadIdx.x == 0) { g_SABS[t] = sa; g_CNT[t] = cnt; }
}

__global__ void finalize_kernel(float* __restrict__ out) {
    int t = threadIdx.x;
    float sp = 0.f, act = 0.f;
    if (t < NT) {
        int g, tl; decode_t(t, g, tl);
        int r = 512 >> g;
        float frob = sqrtf(g_SQU[t] * g_SQV[t]) * rsqrtf((float)(DM * r));
        sp  = tanhf(g_SABS[t] / (float)BATCH) * frob;
        act = g_CNT[t];
    }
    __shared__ float s1[128], s2[128];
    s1[t] = sp; s2[t] = act;
    __syncthreads();
    for (int s = 64; s > 0; s >>= 1) {
        if (t < s) { s1[t] += s1[t + s]; s2[t] += s2[t + s]; }
        __syncthreads();
    }
    if (t == 0) {
        out[SP_OFF]  = s1[0];
        out[ACT_OFF] = s2[0] / (float)BATCH;
    }
}

// ============== mma.sync tf32 GEMMs ==============
// MODE 1: g_Y[m,n] = rna( (Xr @ Vr^T)[m,n] * gate[m,t(n)] )   M=4096 N=10240 K=768
// MODE 2: g_P[z][m,d] = (Y @ W2^T)[m,d], K split 2x5120        M=4096 N=768
// Tiles: BM=BN=128, BK=32, 256 threads, warp=64x32 (4x4 m16n8k8), 3-stage cp.async.
// SMEM swizzle: float offset = row*32 + (k ^ 4*(row&7))  -> conflict-free LDS + 16B stores.
#define STGF 8192                 // floats per stage (As 4096 + Bs 4096)
#define SMEMSZ (3 * STGF * 4)     // 96 KB

template<int MODE>
__global__ void __launch_bounds__(256) gemm_mma() {
    extern __shared__ float sm[];
    const int Kdim = (MODE == 1) ? DM : NRT;
    const int NC   = (MODE == 1) ? 24 : 160;
    const float* __restrict__ A = (MODE == 1) ? g_Xr : g_Y;
    const float* __restrict__ B = (MODE == 1) ? g_Vr : g_W2;
    const int bm = blockIdx.y * 128;
    const int bn = blockIdx.x * 128;
    const int kb0 = (MODE == 2) ? blockIdx.z * 5120 : 0;
    const int tid = threadIdx.x;
    const int lane = tid & 31, w = tid >> 5;
    const int gq = lane >> 2, tig = lane & 3;
    const int wm = w & 1, wn = w >> 1;          // M0 = wm*64, N0 = wn*32

    float c[4][4][4];
#pragma unroll
    for (int i = 0; i < 4; i++)
#pragma unroll
        for (int j = 0; j < 4; j++)
#pragma unroll
            for (int q = 0; q < 4; q++) c[i][j][q] = 0.f;

    const uint32_t smb = smem_u32(sm);

#define LOAD_STAGE(s, cidx) do { \
    uint32_t stb = smb + (uint32_t)(s) * (STGF * 4); \
    int kb = kb0 + (cidx) * 32; \
    _Pragma("unroll") \
    for (int t_ = 0; t_ < 8; t_++) { \
        int idx = tid + t_ * 256; \
        int isB = idx >> 10, rem = idx & 1023; \
        int row = rem >> 3, j = rem & 7; \
        uint32_t dst = stb + (uint32_t)(isB * 16384 + row * 128 + ((j ^ (row & 7)) << 4)); \
        const float* src = (isB ? B + (size_t)(bn + row) * Kdim : A + (size_t)(bm + row) * Kdim) + kb + j * 4; \
        cp16(dst, src); \
    } \
    asm volatile("cp.async.commit_group;" ::: "memory"); \
} while (0)

    LOAD_STAGE(0, 0);
    LOAD_STAGE(1, 1);

    for (int i = 0; i < NC; i++) {
        asm volatile("cp.async.wait_group 1;" ::: "memory");
        __syncthreads();
        if (i + 2 < NC) {
            LOAD_STAGE((i + 2) % 3, i + 2);
        } else {
            asm volatile("cp.async.commit_group;" ::: "memory");
        }
        const uint32_t* Asu = (const uint32_t*)(sm + (i % 3) * STGF);
        const uint32_t* Bsu = Asu + 4096;
#pragma unroll
        for (int ks = 0; ks < 4; ks++) {
            const int k0 = ks * 8 + tig;
            const int sw = gq << 2;
            uint32_t a[4][4], b[4][2];
#pragma unroll
            for (int mt = 0; mt < 4; mt++) {
                int r0 = wm * 64 + mt * 16 + gq;
                a[mt][0] = Asu[r0 * 32 + (k0 ^ sw)];
                a[mt][1] = Asu[(r0 + 8) * 32 + (k0 ^ sw)];
                a[mt][2] = Asu[r0 * 32 + ((k0 + 4) ^ sw)];
                a[mt][3] = Asu[(r0 + 8) * 32 + ((k0 + 4) ^ sw)];
            }
#pragma unroll
            for (int nt = 0; nt < 4; nt++) {
                int rn = wn * 32 + nt * 8 + gq;
                b[nt][0] = Bsu[rn * 32 + (k0 ^ sw)];
                b[nt][1] = Bsu[rn * 32 + ((k0 + 4) ^ sw)];
            }
#pragma unroll
            for (int mt = 0; mt < 4; mt++)
#pragma unroll
                for (int nt = 0; nt < 4; nt++)
                    mma_tf32(c[mt][nt], a[mt], b[nt]);
        }
    }

    // epilogue: c[mt][nt][q] -> row = bm+wm*64+mt*16+gq+(q>>1)*8, col = bn+wn*32+nt*8+2*tig+(q&1)
    if (MODE == 1) {
#pragma unroll
        for (int mt = 0; mt < 4; mt++) {
#pragma unroll
            for (int rr = 0; rr < 2; rr++) {
                int m = bm + wm * 64 + mt * 16 + gq + rr * 8;
                const float* grow = g_GATE + (size_t)m * 128;
                float* yrow = g_Y + (size_t)m * NRT;
#pragma unroll
                for (int nt = 0; nt < 4; nt++) {
                    int colg = bn + wn * 32 + nt * 8 + 2 * tig;
                    int gg = colg >> 11;
                    int t = c_tbase[gg] + ((colg & 2047) >> c_shift[gg]);
                    float gv = grow[t];
                    float2 v;
                    v.x = rna_tf32(c[mt][nt][rr * 2 + 0] * gv);
                    v.y = rna_tf32(c[mt][nt][rr * 2 + 1] * gv);
                    *(float2*)(yrow + colg) = v;
                }
            }
        }
    } else {
        float* P = g_P + (size_t)blockIdx.z * ((size_t)BATCH * DM);
#pragma unroll
        for (int mt = 0; mt < 4; mt++) {
#pragma unroll
            for (int rr = 0; rr < 2; rr++) {
                int m = bm + wm * 64 + mt * 16 + gq + rr * 8;
                float* prow = P + (size_t)m * DM;
#pragma unroll
                for (int nt = 0; nt < 4; nt++) {
                    int colg = bn + wn * 32 + nt * 8 + 2 * tig;
                    float2 v = make_float2(c[mt][nt][rr * 2 + 0], c[mt][nt][rr * 2 + 1]);
                    *(float2*)(prow + colg) = v;
                }
            }
        }
    }
}

__global__ void sum2_kernel(float* __restrict__ OUT) {
    size_t i = (size_t)blockIdx.x * 256 + threadIdx.x;   // < 786432
    const size_t N4 = (size_t)BATCH * DM / 4;
    const float4* p = (const float4*)g_P;
    float4 a = p[i], b = p[i + N4];
    ((float4*)OUT)[i] = make_float4(a.x + b.x, a.y + b.y, a.z + b.z, a.w + b.w);
}

// ============== launch ==============
extern "C" void kernel_launch(void* const* d_in, const int* in_sizes, int n_in,
                              void* d_out, int out_size) {
    (void)in_sizes; (void)n_in; (void)out_size;
    const float* x = (const float*)d_in[0];
    P5 V, U, E, Bv;
    const int rr[5] = {512, 256, 128, 64, 32};
    for (int g = 0; g < 5; g++) {
        V.p[g]  = (const float*)d_in[1 + 4 * g];
        U.p[g]  = (const float*)d_in[2 + 4 * g];
        E.p[g]  = (const float*)d_in[3 + 4 * g];
        Bv.p[g] = (const float*)d_in[4 + 4 * g];
    }
    float* out = (float*)d_out;

    cudaFuncSetAttribute(gemm_mma<1>, cudaFuncAttributeMaxDynamicSharedMemorySize, SMEMSZ);
    cudaFuncSetAttribute(gemm_mma<2>, cudaFuncAttributeMaxDynamicSharedMemorySize, SMEMSZ);

    prep_enc<<<NT, 256>>>(E, Bv);
    rnd_x<<<3072, 256>>>(x);
    rnd_v<<<7680, 256>>>(V);
    for (int g = 0; g < 5; g++)
        build_w2<<<1536, 256>>>(U.p[g], rr[g], g);
    norms_kernel<<<NT, 256>>>(V, U);
    gate_kernel<<<BATCH / 32, 256>>>(x, out);
    gate_stats<<<NT, 256>>>();
    finalize_kernel<<<1, 128>>>(out);

    gemm_mma<1><<<dim3(NRT / 128, BATCH / 128), 256, SMEMSZ>>>();
    gemm_mma<2><<<dim3(DM / 128, BATCH / 128, 2), 256, SMEMSZ>>>();
    sum2_kernel<<<3072, 256>>>(out);
}